// round 15
// baseline (speedup 1.0000x reference)
#include <cuda_runtime.h>
#include <math.h>
#include <stdint.h>

#define B_  8
#define S_  1024
#define H_  512
#define NH_ 8
#define HD_ 64

// Scratch (device globals). Values stored already tf32-quantized.
__device__ float g_q [B_*NH_*S_*HD_];    // [B,NH,S,HD], pre-scaled by 1/8
__device__ float g_k [B_*NH_*S_*HD_];    // [B,NH,S,HD]
__device__ float g_vt[B_*NH_*HD_*S_];    // [B,NH,HD,S] transposed V
__device__ float g_xq[B_*S_*H_];         // quantized hidden
__device__ float g_wq[3*H_*H_];          // quantized Wq|Wk|Wv

__device__ __forceinline__ float to_tf32(float x) {
    unsigned u;
    asm("cvt.rna.tf32.f32 %0, %1;" : "=r"(u) : "f"(x));
    return __uint_as_float(u);
}

__device__ __forceinline__ void mma8(float c[4], const float a[4], float b0, float b1) {
    asm volatile(
        "mma.sync.aligned.m16n8k8.row.col.f32.tf32.tf32.f32 "
        "{%0,%1,%2,%3}, {%4,%5,%6,%7}, {%8,%9}, {%0,%1,%2,%3};\n"
        : "+f"(c[0]), "+f"(c[1]), "+f"(c[2]), "+f"(c[3])
        : "r"(__float_as_uint(a[0])), "r"(__float_as_uint(a[1])),
          "r"(__float_as_uint(a[2])), "r"(__float_as_uint(a[3])),
          "r"(__float_as_uint(b0)), "r"(__float_as_uint(b1)));
}

__device__ __forceinline__ uint32_t smem_u32(const void* p) {
    uint32_t a;
    asm("{ .reg .u64 t; cvta.to.shared.u64 t, %1; cvt.u32.u64 %0, t; }" : "=r"(a) : "l"(p));
    return a;
}
__device__ __forceinline__ void cp16(uint32_t smem, const float* g) {
    asm volatile("cp.async.cg.shared.global [%0], [%1], 16;" :: "r"(smem), "l"(g));
}

// ---------------------------------------------------------------------------
// Prequant: tf32-quantize X and the 3 weight matrices into scratch.
// ---------------------------------------------------------------------------
__global__ __launch_bounds__(256) void quant_kernel(
    const float* __restrict__ X,
    const float* __restrict__ Wq, const float* __restrict__ Wk,
    const float* __restrict__ Wv)
{
    const int NX = (B_*S_*H_) / 4;
    const int NW = (H_*H_) / 4;
    int i = blockIdx.x * 256 + threadIdx.x;
    if (i < NX) {
        float4 v = ((const float4*)X)[i];
        ((float4*)g_xq)[i] = make_float4(to_tf32(v.x), to_tf32(v.y), to_tf32(v.z), to_tf32(v.w));
    } else {
        int j = i - NX;
        int w = j / NW, r = j % NW;
        const float* src = (w == 0) ? Wq : (w == 1) ? Wk : Wv;
        float4 v = ((const float4*)src)[r];
        ((float4*)g_wq)[(size_t)w * NW + r] =
            make_float4(to_tf32(v.x), to_tf32(v.y), to_tf32(v.z), to_tf32(v.w));
    }
}

// ---------------------------------------------------------------------------
// Projection (R14 version): CTA 128x128, k-chunk 32, cp.async double-buffered.
// grid (64, 4, 3), 256 threads (8 warps = 4m x 2n, warp tile 32x64).
// ---------------------------------------------------------------------------
#define PROJ_SMEM 73728

__global__ __launch_bounds__(256, 2) void proj_kernel(
    const float* __restrict__ bq, const float* __restrict__ bk,
    const float* __restrict__ bv)
{
    extern __shared__ float psm[];
    const uint32_t xs_b = smem_u32(psm);
    const uint32_t ws_b = xs_b + 36864u;

    const int zw = blockIdx.z;
    const float* bb = (zw == 0) ? bq : (zw == 1) ? bk : bv;
    const float* Xg = g_xq;
    const float* Wg = g_wq + (size_t)zw * (H_*H_);

    const int m0 = blockIdx.x * 128;
    const int n0 = blockIdx.y * 128;
    const int tid  = threadIdx.x;
    const int lane = tid & 31;
    const int wid  = tid >> 5;
    const int wm = (wid & 3) * 32;
    const int wn = (wid >> 2) * 64;
    const int g = lane >> 2;
    const int t = lane & 3;

    float acc[2][8][4];
#pragma unroll
    for (int i = 0; i < 2; i++)
#pragma unroll
        for (int j = 0; j < 8; j++)
#pragma unroll
            for (int r = 0; r < 4; r++) acc[i][j][r] = 0.f;

#define STAGE_P(IT, BUF) do {                                                  \
        int _kc = (IT) * 32;                                                   \
        _Pragma("unroll")                                                      \
        for (int _j = 0; _j < 4; _j++) {                                       \
            int c = tid + _j * 256;                                            \
            int r = c >> 3, c16 = c & 7;                                       \
            cp16(xs_b + (BUF) * 18432u + r * 144u + c16 * 16u,                 \
                 &Xg[(size_t)(m0 + r) * 512 + _kc + c16 * 4]);                 \
        }                                                                      \
        _Pragma("unroll")                                                      \
        for (int _j = 0; _j < 4; _j++) {                                       \
            int c = tid + _j * 256;                                            \
            int r = c >> 3, c16 = c & 7;                                       \
            cp16(ws_b + (BUF) * 18432u + r * 144u + c16 * 16u,                 \
                 &Wg[(size_t)(n0 + r) * 512 + _kc + c16 * 4]);                 \
        }                                                                      \
    } while (0)

    STAGE_P(0, 0);
    asm volatile("cp.async.commit_group;");

    for (int it = 0; it < 16; it++) {
        const int buf = it & 1;
        if (it + 1 < 16) {
            STAGE_P(it + 1, buf ^ 1);
            asm volatile("cp.async.commit_group;");
            asm volatile("cp.async.wait_group 1;");
        } else {
            asm volatile("cp.async.wait_group 0;");
        }
        __syncthreads();

        const float* Xs = psm + buf * 4608;
        const float* Ws = psm + 9216 + buf * 4608;
#pragma unroll
        for (int kk = 0; kk < 4; kk++) {
            float a[2][4];
#pragma unroll
            for (int i = 0; i < 2; i++) {
                int r = wm + i * 16 + g;
                a[i][0] = Xs[(r    ) * 36 + kk * 8 + t];
                a[i][1] = Xs[(r + 8) * 36 + kk * 8 + t];
                a[i][2] = Xs[(r    ) * 36 + kk * 8 + t + 4];
                a[i][3] = Xs[(r + 8) * 36 + kk * 8 + t + 4];
            }
#pragma unroll
            for (int j = 0; j < 8; j++) {
                int r = wn + j * 8 + g;
                float b0 = Ws[r * 36 + kk * 8 + t];
                float b1 = Ws[r * 36 + kk * 8 + t + 4];
#pragma unroll
                for (int i = 0; i < 2; i++) mma8(acc[i][j], a[i], b0, b1);
            }
        }
        __syncthreads();
    }

#pragma unroll
    for (int i = 0; i < 2; i++) {
#pragma unroll
        for (int j = 0; j < 8; j++) {
            int n = n0 + wn + j * 8 + t * 2;
            float b0 = bb[n], b1 = bb[n + 1];
            int h = n >> 6, d = n & 63;
#pragma unroll
            for (int rr = 0; rr < 2; rr++) {
                int m = m0 + wm + i * 16 + g + rr * 8;
                int bI = m >> 10, s = m & 1023;
                float v0 = acc[i][j][rr * 2 + 0] + b0;
                float v1 = acc[i][j][rr * 2 + 1] + b1;
                if (zw == 0) {
                    float* dst = &g_q[(((bI * NH_ + h) * S_) + s) * HD_ + d];
                    dst[0] = to_tf32(v0 * 0.125f);
                    dst[1] = to_tf32(v1 * 0.125f);
                } else if (zw == 1) {
                    float* dst = &g_k[(((bI * NH_ + h) * S_) + s) * HD_ + d];
                    dst[0] = to_tf32(v0);
                    dst[1] = to_tf32(v1);
                } else {
                    g_vt[(((bI * NH_ + h) * HD_) + d    ) * S_ + s] = to_tf32(v0);
                    g_vt[(((bI * NH_ + h) * HD_) + d + 1) * S_ + s] = to_tf32(v1);
                }
            }
        }
    }
}

// ---------------------------------------------------------------------------
// Flash attention: warp q-tile 32 rows (2 m-tiles) -> 1.0 LDS/MMA.
// grid (8, NH, B), 128 threads = 4 warps x 32 q-rows, k-block 32.
// cp.async double-buffered K/Vt; shuffle P conversion; shift-free softmax.
// Dyn SMEM floats: K 2x32x68 [0,4352), Vt 2x64x36 [4352,8960) = 35840 B.
// ---------------------------------------------------------------------------
#define ATTN_SMEM 35840

__global__ __launch_bounds__(128, 3) void attn_kernel(
    const float* __restrict__ rel,   // [B,NH,S,S]
    const float* __restrict__ mask,  // [B,1,1,S]
    float* __restrict__ out)         // [B,S,H]
{
    extern __shared__ float asm_[];
    const uint32_t ks_base = smem_u32(asm_);
    const uint32_t vs_base = ks_base + 17408u;

    const int b = blockIdx.z, h = blockIdx.y;
    const int q0 = blockIdx.x * 128;
    const int tid  = threadIdx.x;
    const int lane = tid & 31;
    const int wid  = tid >> 5;
    const int wq = wid * 32;
    const int g = lane >> 2;
    const int t = lane & 3;
    const size_t bh = (size_t)(b * NH_ + h);

    const float* Kg = &g_k[(bh * S_) * 64];
    const float* Vg = &g_vt[(bh * 64) * (size_t)S_];
    const float* mbase = mask + b * S_;
    const float* rw00 = rel + (bh * S_ + q0 + wq + g     ) * S_;
    const float* rw01 = rel + (bh * S_ + q0 + wq + g +  8) * S_;
    const float* rw10 = rel + (bh * S_ + q0 + wq + g + 16) * S_;
    const float* rw11 = rel + (bh * S_ + q0 + wq + g + 24) * S_;

    // Q fragments resident: 2 m-tiles x 8 kk x 4
    float qa[2][8][4];
    {
        const float* Qp = &g_q[(bh * S_ + q0 + wq) * HD_];
#pragma unroll
        for (int mt = 0; mt < 2; mt++)
#pragma unroll
            for (int kk = 0; kk < 8; kk++) {
                int rr = mt * 16 + g;
                qa[mt][kk][0] = Qp[(rr    ) * 64 + kk * 8 + t];
                qa[mt][kk][1] = Qp[(rr + 8) * 64 + kk * 8 + t];
                qa[mt][kk][2] = Qp[(rr    ) * 64 + kk * 8 + t + 4];
                qa[mt][kk][3] = Qp[(rr + 8) * 64 + kk * 8 + t + 4];
            }
    }

    float o[2][8][4];
#pragma unroll
    for (int mt = 0; mt < 2; mt++)
#pragma unroll
        for (int i = 0; i < 8; i++)
#pragma unroll
            for (int r = 0; r < 4; r++) o[mt][i][r] = 0.f;

    float l00 = 0.f, l01 = 0.f, l10 = 0.f, l11 = 0.f;

    // staging: 128 threads, 4 x 16B chunks each for K and V
#define STAGE_TILE(ITER, BUF) do {                                            \
        int _kb = (ITER) * 32;                                                \
        _Pragma("unroll")                                                     \
        for (int _j = 0; _j < 4; _j++) {                                      \
            int c = tid + _j * 128;                                           \
            int r = c >> 4, c16 = c & 15;                                     \
            cp16(ks_base + (BUF) * 8704u + r * 272u + c16 * 16u,              \
                 &Kg[(size_t)(_kb + r) * 64 + c16 * 4]);                      \
        }                                                                     \
        _Pragma("unroll")                                                     \
        for (int _j = 0; _j < 4; _j++) {                                      \
            int c = tid + _j * 128;                                           \
            int r = c >> 3, c16 = c & 7;                                      \
            cp16(vs_base + (BUF) * 9216u + r * 144u + c16 * 16u,              \
                 &Vg[(size_t)r * S_ + _kb + c16 * 4]);                        \
        }                                                                     \
    } while (0)

    STAGE_TILE(0, 0);
    asm volatile("cp.async.commit_group;");

    const int srcA = (g << 2) + (t >> 1);
    const int srcB = srcA + 2;
    const bool podd = (t & 1);

    for (int it = 0; it < 32; it++) {
        const int buf = it & 1;
        const int kb = it * 32;

        if (it + 1 < 32) {
            STAGE_TILE(it + 1, buf ^ 1);
            asm volatile("cp.async.commit_group;");
            asm volatile("cp.async.wait_group 1;");
        } else {
            asm volatile("cp.async.wait_group 0;");
        }
        __syncthreads();

        const float* Ks = asm_ + buf * 2176;          // [k 32][d 68]
        const float* Vs = asm_ + 4352 + buf * 2304;   // [d 64][k 36]

        // ---- S = Q K^T (32 x 32): B-frag shared across 2 m-tiles
        float s[2][4][4];
#pragma unroll
        for (int mt = 0; mt < 2; mt++)
#pragma unroll
            for (int nf = 0; nf < 4; nf++)
#pragma unroll
                for (int r = 0; r < 4; r++) s[mt][nf][r] = 0.f;
#pragma unroll
        for (int kk = 0; kk < 8; kk++) {
#pragma unroll
            for (int nf = 0; nf < 4; nf++) {
                float b0 = Ks[(nf * 8 + g) * 68 + kk * 8 + t];
                float b1 = Ks[(nf * 8 + g) * 68 + kk * 8 + t + 4];
                mma8(s[0][nf], qa[0][kk], b0, b1);
                mma8(s[1][nf], qa[1][kk], b0, b1);
            }
        }

        // ---- + rel + mask, exp (no shift), accumulate l, quantize
#pragma unroll
        for (int nf = 0; nf < 4; nf++) {
            int col = kb + nf * 8 + t * 2;
            float2 mk = *(const float2*)&mbase[col];
            float2 a0 = *(const float2*)&rw00[col];
            float2 a1 = *(const float2*)&rw01[col];
            float2 a2 = *(const float2*)&rw10[col];
            float2 a3 = *(const float2*)&rw11[col];
            float e00 = to_tf32(__expf(s[0][nf][0] + a0.x + mk.x));
            float e01 = to_tf32(__expf(s[0][nf][1] + a0.y + mk.y));
            float e02 = to_tf32(__expf(s[0][nf][2] + a1.x + mk.x));
            float e03 = to_tf32(__expf(s[0][nf][3] + a1.y + mk.y));
            float e10 = to_tf32(__expf(s[1][nf][0] + a2.x + mk.x));
            float e11 = to_tf32(__expf(s[1][nf][1] + a2.y + mk.y));
            float e12 = to_tf32(__expf(s[1][nf][2] + a3.x + mk.x));
            float e13 = to_tf32(__expf(s[1][nf][3] + a3.y + mk.y));
            l00 += e00 + e01;  l01 += e02 + e03;
            l10 += e10 + e11;  l11 += e12 + e13;
            s[0][nf][0] = e00; s[0][nf][1] = e01; s[0][nf][2] = e02; s[0][nf][3] = e03;
            s[1][nf][0] = e10; s[1][nf][1] = e11; s[1][nf][2] = e12; s[1][nf][3] = e13;
        }

        // ---- O += P V : shuffle-convert per (mt,nf); V B-frag shared across mt
#pragma unroll
        for (int nf = 0; nf < 4; nf++) {
            float a0[4], a1[4];
#pragma unroll
            for (int mt = 0; mt < 2; mt++) {
                float x0 = __shfl_sync(0xffffffffu, s[mt][nf][0], srcA);
                float x1 = __shfl_sync(0xffffffffu, s[mt][nf][1], srcA);
                float y0 = __shfl_sync(0xffffffffu, s[mt][nf][2], srcA);
                float y1 = __shfl_sync(0xffffffffu, s[mt][nf][3], srcA);
                float z0 = __shfl_sync(0xffffffffu, s[mt][nf][0], srcB);
                float z1 = __shfl_sync(0xffffffffu, s[mt][nf][1], srcB);
                float w0 = __shfl_sync(0xffffffffu, s[mt][nf][2], srcB);
                float w1 = __shfl_sync(0xffffffffu, s[mt][nf][3], srcB);
                float* a = mt ? a1 : a0;
                a[0] = podd ? x1 : x0;
                a[1] = podd ? y1 : y0;
                a[2] = podd ? z1 : z0;
                a[3] = podd ? w1 : w0;
            }
#pragma unroll
            for (int nd = 0; nd < 8; nd++) {
                float b0 = Vs[(nd * 8 + g) * 36 + nf * 8 + t];
                float b1 = Vs[(nd * 8 + g) * 36 + nf * 8 + t + 4];
                mma8(o[0][nd], a0, b0, b1);
                mma8(o[1][nd], a1, b0, b1);
            }
        }
        __syncthreads();
    }

    // ---- l reduce over quad
    l00 += __shfl_xor_sync(0xffffffffu, l00, 1);
    l00 += __shfl_xor_sync(0xffffffffu, l00, 2);
    l01 += __shfl_xor_sync(0xffffffffu, l01, 1);
    l01 += __shfl_xor_sync(0xffffffffu, l01, 2);
    l10 += __shfl_xor_sync(0xffffffffu, l10, 1);
    l10 += __shfl_xor_sync(0xffffffffu, l10, 2);
    l11 += __shfl_xor_sync(0xffffffffu, l11, 1);
    l11 += __shfl_xor_sync(0xffffffffu, l11, 2);

#pragma unroll
    for (int mt = 0; mt < 2; mt++) {
        float inv0 = 1.f / (mt ? l10 : l00);
        float inv1 = 1.f / (mt ? l11 : l01);
        int q = q0 + wq + mt * 16 + g;
        float* ob0 = &out[((size_t)(b * S_ + q    )) * H_ + h * 64];
        float* ob1 = &out[((size_t)(b * S_ + q + 8)) * H_ + h * 64];
#pragma unroll
        for (int nd = 0; nd < 8; nd++) {
            int c = nd * 8 + t * 2;
            *(float2*)&ob0[c] = make_float2(o[mt][nd][0] * inv0, o[mt][nd][1] * inv0);
            *(float2*)&ob1[c] = make_float2(o[mt][nd][2] * inv1, o[mt][nd][3] * inv1);
        }
    }
}

// ---------------------------------------------------------------------------
extern "C" void kernel_launch(void* const* d_in, const int* in_sizes, int n_in,
                              void* d_out, int out_size)
{
    const float* hidden = (const float*)d_in[0];
    const float* mask   = (const float*)d_in[1];
    const float* rel    = (const float*)d_in[2];
    const float* Wq     = (const float*)d_in[3];
    const float* bq     = (const float*)d_in[4];
    const float* Wk     = (const float*)d_in[5];
    const float* bk     = (const float*)d_in[6];
    const float* Wv     = (const float*)d_in[7];
    const float* bv     = (const float*)d_in[8];
    float* out = (float*)d_out;

    cudaFuncSetAttribute(proj_kernel, cudaFuncAttributeMaxDynamicSharedMemorySize, PROJ_SMEM);
    cudaFuncSetAttribute(attn_kernel, cudaFuncAttributeMaxDynamicSharedMemorySize, ATTN_SMEM);

    int nq = (B_*S_*H_ + 3*H_*H_) / 4 / 256;
    quant_kernel<<<nq, 256>>>(hidden, Wq, Wk, Wv);

    dim3 pg(64, 4, 3);
    proj_kernel<<<pg, 256, PROJ_SMEM>>>(bq, bk, bv);

    dim3 ag(8, NH_, B_);
    attn_kernel<<<ag, 128, ATTN_SMEM>>>(rel, mask, out);
}